// round 1
// baseline (speedup 1.0000x reference)
#include <cuda_runtime.h>
#include <math.h>

#define B_   2
#define S_   256
#define D_   1024
#define H_   8
#define L_   16
#define FF_  2048
#define V_   50257
#define HD_  128
#define SB_  (S_*B_)      // 512
#define SBD_ (SB_*D_)     // 524288

// ---------------- scratch (device globals: no allocation allowed) ----------------
static __device__ float g_x0[SBD_];
static __device__ float g_lo[L_*SBD_];
static __device__ float g_q[SBD_];
static __device__ float g_k[15*SBD_];
static __device__ float g_v[15*SBD_];
static __device__ float g_sc[15*16*S_*S_];
static __device__ float g_comb[SBD_];
static __device__ float g_xa[SBD_];
static __device__ float g_t2[SBD_];
static __device__ float g_tff[SB_*FF_];
static __device__ float g_sp[SBD_];
static __device__ float g_dw[L_*16];

// ---------------- generic SGEMM: C = act(A@B + bias) ----------------
// A row-major [M,K] lda, B row-major [K,N] ldb, C [M,N] ldc.
// BM=BN=64, BK=16, 256 threads, 4x4 per thread.
// OUTBS: remap output row m=(s*B+b) -> (b*S+s) for final [B,S,V] transpose.
template<bool RELU, bool OUTBS>
__global__ void __launch_bounds__(256) sgemm_kernel(
    int M, int N, int K,
    const float* __restrict__ A, int lda,
    const float* __restrict__ Bm, int ldb,
    const float* __restrict__ bias,
    float* __restrict__ C, int ldc)
{
    __shared__ float As[16][68];
    __shared__ float Bs[16][68];
    int tid = threadIdx.x;
    int tx = tid & 15, ty = tid >> 4;
    int m0 = blockIdx.y << 6, n0 = blockIdx.x << 6;
    int arow = tid >> 2, ak = (tid & 3) << 2;
    int brow = tid >> 4, bn = (tid & 15) << 2;
    float acc[4][4] = {};
    const float* Ap = A + (size_t)(m0 + arow)*lda + ak;
    for (int k0 = 0; k0 < K; k0 += 16) {
        #pragma unroll
        for (int i = 0; i < 4; i++) As[ak+i][arow] = Ap[k0 + i];
        #pragma unroll
        for (int i = 0; i < 4; i++) {
            int n = n0 + bn + i;
            Bs[brow][bn+i] = (n < N) ? Bm[(size_t)(k0 + brow)*ldb + n] : 0.f;
        }
        __syncthreads();
        #pragma unroll
        for (int kk = 0; kk < 16; kk++) {
            float4 a4 = *(const float4*)&As[kk][ty << 2];
            float4 b4 = *(const float4*)&Bs[kk][tx << 2];
            float av[4] = {a4.x, a4.y, a4.z, a4.w};
            float bv[4] = {b4.x, b4.y, b4.z, b4.w};
            #pragma unroll
            for (int i = 0; i < 4; i++)
                #pragma unroll
                for (int j = 0; j < 4; j++)
                    acc[i][j] += av[i] * bv[j];
        }
        __syncthreads();
    }
    #pragma unroll
    for (int i = 0; i < 4; i++) {
        int m = m0 + (ty << 2) + i;
        int orow = OUTBS ? ((m & 1)*S_ + (m >> 1)) : m;
        #pragma unroll
        for (int j = 0; j < 4; j++) {
            int n = n0 + (tx << 2) + j;
            if (n < N) {
                float v = acc[i][j] + bias[n];
                if (RELU) v = fmaxf(v, 0.f);
                C[(size_t)orow*ldc + n] = v;
            }
        }
    }
}

// ---------------- scores: P[src,bh,q,k] = SCALE * q_bh . k_src,bh ----------------
// q rows/k rows have stride B*D (=2048) in the [S,B,D] projection buffers.
__global__ void __launch_bounds__(256) qk_kernel(
    const float* __restrict__ Q, const float* __restrict__ Kb, float* __restrict__ P)
{
    __shared__ float As[16][68];
    __shared__ float Bs[16][68];
    int z = blockIdx.z;
    int src = z >> 4, bh = z & 15;
    const float* Aq = Q + bh*HD_;
    const float* Bk = Kb + (size_t)src*SBD_ + bh*HD_;
    float* Cp = P + (size_t)z*S_*S_;
    int tid = threadIdx.x;
    int tx = tid & 15, ty = tid >> 4;
    int m0 = blockIdx.y << 6, n0 = blockIdx.x << 6;
    int arow = tid >> 2, ak = (tid & 3) << 2;
    float acc[4][4] = {};
    for (int k0 = 0; k0 < HD_; k0 += 16) {
        #pragma unroll
        for (int i = 0; i < 4; i++) As[ak+i][arow] = Aq[(size_t)(m0 + arow)*(B_*D_) + k0 + ak + i];
        #pragma unroll
        for (int i = 0; i < 4; i++) Bs[ak+i][arow] = Bk[(size_t)(n0 + arow)*(B_*D_) + k0 + ak + i];
        __syncthreads();
        #pragma unroll
        for (int kk = 0; kk < 16; kk++) {
            float4 a4 = *(const float4*)&As[kk][ty << 2];
            float4 b4 = *(const float4*)&Bs[kk][tx << 2];
            float av[4] = {a4.x, a4.y, a4.z, a4.w};
            float bv[4] = {b4.x, b4.y, b4.z, b4.w};
            #pragma unroll
            for (int i = 0; i < 4; i++)
                #pragma unroll
                for (int j = 0; j < 4; j++)
                    acc[i][j] += av[i] * bv[j];
        }
        __syncthreads();
    }
    const float scale = 0.0883883476483184f; // 1/sqrt(128)
    #pragma unroll
    for (int i = 0; i < 4; i++)
        #pragma unroll
        for (int j = 0; j < 4; j++)
            Cp[(size_t)(m0 + (ty<<2) + i)*S_ + n0 + (tx<<2) + j] = acc[i][j] * scale;
}

// ---------------- softmax over keys + apply layer weight -------------------------
// One warp per row of 256; P row r belongs to source r>>12.
__global__ void __launch_bounds__(256) softmax_kernel(float* __restrict__ P,
                                                      const float* __restrict__ dwl)
{
    int r = blockIdx.x*8 + (threadIdx.x >> 5);
    int lane = threadIdx.x & 31;
    float* row = P + (size_t)r*256;
    float w = dwl[r >> 12];
    float v[8];
    #pragma unroll
    for (int i = 0; i < 8; i++) v[i] = row[lane*8 + i];
    float mx = v[0];
    #pragma unroll
    for (int i = 1; i < 8; i++) mx = fmaxf(mx, v[i]);
    #pragma unroll
    for (int o = 16; o; o >>= 1) mx = fmaxf(mx, __shfl_xor_sync(0xffffffffu, mx, o));
    float s = 0.f;
    #pragma unroll
    for (int i = 0; i < 8; i++) { v[i] = expf(v[i] - mx); s += v[i]; }
    #pragma unroll
    for (int o = 16; o; o >>= 1) s += __shfl_xor_sync(0xffffffffu, s, o);
    float sc = w / s;
    #pragma unroll
    for (int i = 0; i < 8; i++) row[lane*8 + i] = v[i] * sc;
}

// ---------------- comb: sum over sources of (weighted P) @ V ---------------------
// grid (hd-tile=2, q-tile=4, bh=16). Output written straight into [S,B,D] layout.
__global__ void __launch_bounds__(256) comb_kernel(
    int nsrc, const float* __restrict__ P, const float* __restrict__ Vb,
    float* __restrict__ Cc)
{
    __shared__ float As[16][68];
    __shared__ float Bs[16][68];
    int bh = blockIdx.z, b = bh >> 3, h = bh & 7;
    int tid = threadIdx.x;
    int tx = tid & 15, ty = tid >> 4;
    int m0 = blockIdx.y << 6, n0 = blockIdx.x << 6;
    int arow = tid >> 2, ak = (tid & 3) << 2;
    int brow = tid >> 4, bn = (tid & 15) << 2;
    float acc[4][4] = {};
    for (int src = 0; src < nsrc; src++) {
        const float* Ap = P + ((size_t)src*16 + bh)*S_*S_;
        const float* Bv = Vb + (size_t)src*SBD_ + bh*HD_;
        for (int k0 = 0; k0 < S_; k0 += 16) {
            #pragma unroll
            for (int i = 0; i < 4; i++) As[ak+i][arow] = Ap[(size_t)(m0 + arow)*S_ + k0 + ak + i];
            #pragma unroll
            for (int i = 0; i < 4; i++) Bs[brow][bn+i] = Bv[(size_t)(k0 + brow)*(B_*D_) + n0 + bn + i];
            __syncthreads();
            #pragma unroll
            for (int kk = 0; kk < 16; kk++) {
                float4 a4 = *(const float4*)&As[kk][ty << 2];
                float4 b4 = *(const float4*)&Bs[kk][tx << 2];
                float av[4] = {a4.x, a4.y, a4.z, a4.w};
                float bv[4] = {b4.x, b4.y, b4.z, b4.w};
                #pragma unroll
                for (int i = 0; i < 4; i++)
                    #pragma unroll
                    for (int j = 0; j < 4; j++)
                        acc[i][j] += av[i] * bv[j];
            }
            __syncthreads();
        }
    }
    #pragma unroll
    for (int i = 0; i < 4; i++) {
        int q = m0 + (ty << 2) + i;
        #pragma unroll
        for (int j = 0; j < 4; j++)
            Cc[(size_t)(q*B_ + b)*D_ + h*HD_ + n0 + (tx<<2) + j] = acc[i][j];
    }
}

// ---------------- embedding + sinusoidal positional encoding ---------------------
__global__ void __launch_bounds__(256) embed_kernel(const int* __restrict__ src,
                                                    const float* __restrict__ emb,
                                                    float* __restrict__ X)
{
    int row = blockIdx.x;         // row = s*B + b
    int s = row >> 1, b = row & 1;
    int tok = src[b*S_ + s];
    const float* e = emb + (size_t)tok*D_;
    float* xr = X + (size_t)row*D_;
    const float c = -9.210340371976184f / (float)D_;  // -ln(10000)/D
    #pragma unroll
    for (int i = 0; i < 4; i++) {
        int d = threadIdx.x + (i << 8);
        int ev = d & ~1;
        float div = expf((float)ev * c);
        float arg = (float)s * div;
        float pe = (d & 1) ? cosf(arg) : sinf(arg);
        xr[d] = e[d]*32.0f + pe;   // sqrt(1024)=32
    }
}

// ---------------- distinct-source layer weights ----------------------------------
// softmax(lw[l][:l+1]); srcs = [x]+prevs with x==LO[l-1] duplicated for l>=1:
//   l==0: dw[0] = w0 (source x0)
//   l>=1: dw[j] = w[j+1] + (j==l-1 ? w[0] : 0), j in [0,l)
__global__ void dw_kernel(const float* __restrict__ lw, float* __restrict__ dw)
{
    int l = threadIdx.x;
    if (l >= L_) return;
    int n = l + 1;
    float w[17];
    float mx = -1e30f;
    for (int j = 0; j < n; j++) { w[j] = lw[l*(L_+1) + j]; mx = fmaxf(mx, w[j]); }
    float s = 0.f;
    for (int j = 0; j < n; j++) { w[j] = expf(w[j] - mx); s += w[j]; }
    for (int j = 0; j < n; j++) w[j] /= s;
    if (l == 0) dw[0] = w[0];
    else for (int j = 0; j < l; j++) dw[l*16 + j] = w[j+1] + ((j == l-1) ? w[0] : 0.f);
}

// ---------------- residual add + LayerNorm ----------------------------------------
__global__ void __launch_bounds__(256) addln_kernel(const float* __restrict__ x,
                                                    const float* __restrict__ r,
                                                    const float* __restrict__ g,
                                                    const float* __restrict__ be,
                                                    float* __restrict__ out)
{
    int row = blockIdx.x;
    const float* xr = x + (size_t)row*D_;
    const float* rr = r + (size_t)row*D_;
    int lane = threadIdx.x & 31, wid = threadIdx.x >> 5;
    float v[4];
    float s = 0.f, sq = 0.f;
    #pragma unroll
    for (int i = 0; i < 4; i++) {
        int d = threadIdx.x + (i << 8);
        float a = xr[d] + rr[d];
        v[i] = a; s += a; sq += a*a;
    }
    #pragma unroll
    for (int o = 16; o; o >>= 1) {
        s  += __shfl_xor_sync(0xffffffffu, s, o);
        sq += __shfl_xor_sync(0xffffffffu, sq, o);
    }
    __shared__ float shs[8], shq[8], mv[2];
    if (lane == 0) { shs[wid] = s; shq[wid] = sq; }
    __syncthreads();
    if (wid == 0) {
        float a = (lane < 8) ? shs[lane] : 0.f;
        float b = (lane < 8) ? shq[lane] : 0.f;
        #pragma unroll
        for (int o = 4; o; o >>= 1) {
            a += __shfl_xor_sync(0xffffffffu, a, o);
            b += __shfl_xor_sync(0xffffffffu, b, o);
        }
        if (lane == 0) {
            float mean = a * (1.f/ (float)D_);
            float var  = b * (1.f/ (float)D_) - mean*mean;
            mv[0] = mean; mv[1] = rsqrtf(var + 1e-5f);
        }
    }
    __syncthreads();
    float mean = mv[0], rstd = mv[1];
    float* orow = out + (size_t)row*D_;
    #pragma unroll
    for (int i = 0; i < 4; i++) {
        int d = threadIdx.x + (i << 8);
        orow[d] = (v[i] - mean)*rstd*g[d] + be[d];
    }
}

// ---------------- SNN scan: sequential over S steps, one block per batch ----------
__global__ void __launch_bounds__(256) snn_kernel(const float* __restrict__ cur,
                                                  float* __restrict__ spikes)
{
    int b = blockIdx.x;
    int lane = threadIdx.x & 31, wid = threadIdx.x >> 5;
    float mem[4] = {0.f,0.f,0.f,0.f};
    float thr[4] = {1.f,1.f,1.f,1.f};
    __shared__ float sh[8];
    __shared__ float tot[2];
    for (int t = 0; t < S_; t++) {
        float p = mem[0]+mem[1]+mem[2]+mem[3];
        #pragma unroll
        for (int o = 16; o; o >>= 1) p += __shfl_xor_sync(0xffffffffu, p, o);
        if (lane == 0) sh[wid] = p;
        __syncthreads();
        if (wid == 0) {
            float v = (lane < 8) ? sh[lane] : 0.f;
            #pragma unroll
            for (int o = 4; o; o >>= 1) v += __shfl_xor_sync(0xffffffffu, v, o);
            if (lane == 0) tot[t & 1] = v;
        }
        __syncthreads();
        float M = tot[t & 1];
        const float* cr = cur    + ((size_t)t*B_ + b)*D_;
        float*       sr = spikes + ((size_t)t*B_ + b)*D_;
        #pragma unroll
        for (int i = 0; i < 4; i++) {
            int d = threadIdx.x + (i << 8);
            float c  = cr[d] - 0.1f*M;          // lateral inhibition
            float m2 = 0.9f*mem[i] + c;          // decay + input
            float sp = (m2 >= thr[i]) ? 1.f : 0.f;
            mem[i] = m2 - sp*thr[i];             // soft reset
            thr[i] = 0.9f*thr[i] + 0.1f*sp;      // adaptive threshold
            sr[d] = sp;
        }
    }
}

// ---------------- host orchestration ---------------------------------------------
extern "C" void kernel_launch(void* const* d_in, const int* in_sizes, int n_in,
                              void* d_out, int out_size)
{
    const int*   src  = (const int*)  d_in[0];
    const float* emb  = (const float*)d_in[1];
    const float* Wq   = (const float*)d_in[2];
    const float* bq   = (const float*)d_in[3];
    const float* Wk   = (const float*)d_in[4];
    const float* bk   = (const float*)d_in[5];
    const float* Wv   = (const float*)d_in[6];
    const float* bv   = (const float*)d_in[7];
    const float* Wo   = (const float*)d_in[8];
    const float* bo   = (const float*)d_in[9];
    const float* lw   = (const float*)d_in[10];
    const float* Wsnn = (const float*)d_in[11];
    const float* bsnn = (const float*)d_in[12];
    const float* W1   = (const float*)d_in[13];
    const float* b1   = (const float*)d_in[14];
    const float* W2   = (const float*)d_in[15];
    const float* b2   = (const float*)d_in[16];
    const float* g1   = (const float*)d_in[17];
    const float* be1  = (const float*)d_in[18];
    const float* g2   = (const float*)d_in[19];
    const float* be2  = (const float*)d_in[20];
    const float* Wout = (const float*)d_in[21];
    const float* bout = (const float*)d_in[22];
    float* out = (float*)d_out;

    float *x0,*lo,*q,*kb,*vb,*sc,*comb,*xa,*t2,*tff,*sp,*dw;
    cudaGetSymbolAddress((void**)&x0,   g_x0);
    cudaGetSymbolAddress((void**)&lo,   g_lo);
    cudaGetSymbolAddress((void**)&q,    g_q);
    cudaGetSymbolAddress((void**)&kb,   g_k);
    cudaGetSymbolAddress((void**)&vb,   g_v);
    cudaGetSymbolAddress((void**)&sc,   g_sc);
    cudaGetSymbolAddress((void**)&comb, g_comb);
    cudaGetSymbolAddress((void**)&xa,   g_xa);
    cudaGetSymbolAddress((void**)&t2,   g_t2);
    cudaGetSymbolAddress((void**)&tff,  g_tff);
    cudaGetSymbolAddress((void**)&sp,   g_sp);
    cudaGetSymbolAddress((void**)&dw,   g_dw);

    embed_kernel<<<SB_, 256>>>(src, emb, x0);
    dw_kernel<<<1, 32>>>(lw, dw);

    for (int l = 0; l < L_; l++) {
        int nsrc = (l == 0) ? 1 : l;
        const float* srcbase = (l == 0) ? x0 : lo;                       // distinct sources, contiguous
        const float* xin     = (l == 0) ? x0 : (lo + (size_t)(l-1)*SBD_);// current stream value
        int Ms = nsrc * SB_;

        // K,V projections for ALL distinct sources in one GEMM each
        sgemm_kernel<false,false><<<dim3(D_/64, Ms/64), 256>>>(
            Ms, D_, D_, srcbase, D_, Wk + (size_t)l*D_*D_, D_, bk + l*D_, kb, D_);
        sgemm_kernel<false,false><<<dim3(D_/64, Ms/64), 256>>>(
            Ms, D_, D_, srcbase, D_, Wv + (size_t)l*D_*D_, D_, bv + l*D_, vb, D_);
        // Q projection
        sgemm_kernel<false,false><<<dim3(D_/64, SB_/64), 256>>>(
            SB_, D_, D_, xin, D_, Wq + (size_t)l*D_*D_, D_, bq + l*D_, q, D_);
        // scores, softmax (applies per-source weight), weighted PV
        qk_kernel<<<dim3(4, 4, nsrc*16), 256>>>(q, kb, sc);
        softmax_kernel<<<nsrc*512, 256>>>(sc, dw + l*16);
        comb_kernel<<<dim3(2, 4, 16), 256>>>(nsrc, sc, vb, comb);
        // output projection + residual LN
        sgemm_kernel<false,false><<<dim3(D_/64, SB_/64), 256>>>(
            SB_, D_, D_, comb, D_, Wo + (size_t)l*D_*D_, D_, bo + l*D_, t2, D_);
        addln_kernel<<<SB_, 256>>>(xin, t2, g1 + l*D_, be1 + l*D_, xa);
        // SNN: input current GEMM then sequential scan
        sgemm_kernel<false,false><<<dim3(D_/64, SB_/64), 256>>>(
            SB_, D_, D_, xa, D_, Wsnn + (size_t)l*D_*D_, D_, bsnn + l*D_, t2, D_);
        snn_kernel<<<B_, 256>>>(t2, sp);
        // FFN
        sgemm_kernel<true,false><<<dim3(FF_/64, SB_/64), 256>>>(
            SB_, FF_, D_, sp, D_, W1 + (size_t)l*D_*FF_, FF_, b1 + l*FF_, tff, FF_);
        sgemm_kernel<false,false><<<dim3(D_/64, SB_/64), 256>>>(
            SB_, D_, FF_, tff, FF_, W2 + (size_t)l*FF_*D_, D_, b2 + l*D_, t2, D_);
        addln_kernel<<<SB_, 256>>>(xa, t2, g2 + l*D_, be2 + l*D_, lo + (size_t)l*SBD_);
    }

    // final vocab projection, fused [S,B]->[B,S] transpose on store
    sgemm_kernel<false,true><<<dim3((V_+63)/64, SB_/64), 256>>>(
        SB_, V_, D_, lo + (size_t)15*SBD_, D_, Wout, V_, bout, out, V_);
}

// round 2
// speedup vs baseline: 1.9631x; 1.9631x over previous
#include <cuda_runtime.h>
#include <cuda_bf16.h>
#include <mma.h>
#include <math.h>

using namespace nvcuda;

#define B_   2
#define S_   256
#define D_   1024
#define H_   8
#define L_   16
#define FF_  2048
#define V_   50257
#define HD_  128
#define SB_  (S_*B_)      // 512
#define SBD_ (SB_*D_)     // 524288

// ---------------- scratch (device globals: no allocation allowed) ----------------
static __device__ float g_x0[SBD_];
static __device__ float g_lo[L_*SBD_];
static __device__ float g_q[SBD_];
static __device__ float g_k[15*SBD_];
static __device__ float g_v[15*SBD_];
static __device__ float g_sc[15*16*S_*S_];
static __device__ float g_comb[SBD_];
static __device__ float g_xa[SBD_];
static __device__ float g_t2[SBD_];
static __device__ float g_tff[SB_*FF_];
static __device__ float g_sp[SBD_];
static __device__ float g_dw[L_*16];

// ================== bf16x3 split helpers =========================================
// x = hi + lo with hi = bf16(x), lo = bf16(x - hi). Error ~2^-17 relative.
__device__ __forceinline__ void cvt_store4(float4 v, __nv_bfloat16* hp, __nv_bfloat16* lp)
{
    __nv_bfloat16 h0 = __float2bfloat16(v.x);
    __nv_bfloat16 h1 = __float2bfloat16(v.y);
    __nv_bfloat16 h2 = __float2bfloat16(v.z);
    __nv_bfloat16 h3 = __float2bfloat16(v.w);
    __nv_bfloat16 l0 = __float2bfloat16(v.x - __bfloat162float(h0));
    __nv_bfloat16 l1 = __float2bfloat16(v.y - __bfloat162float(h1));
    __nv_bfloat16 l2 = __float2bfloat16(v.z - __bfloat162float(h2));
    __nv_bfloat16 l3 = __float2bfloat16(v.w - __bfloat162float(h3));
    __nv_bfloat162 th0; th0.x = h0; th0.y = h1;
    __nv_bfloat162 th1; th1.x = h2; th1.y = h3;
    __nv_bfloat162 tl0; tl0.x = l0; tl0.y = l1;
    __nv_bfloat162 tl1; tl1.x = l2; tl1.y = l3;
    *(__nv_bfloat162*)(hp)     = th0;
    *(__nv_bfloat162*)(hp + 2) = th1;
    *(__nv_bfloat162*)(lp)     = tl0;
    *(__nv_bfloat162*)(lp + 2) = tl1;
}
__device__ __forceinline__ void cvt_store1(float x, __nv_bfloat16* hp, __nv_bfloat16* lp)
{
    __nv_bfloat16 h = __float2bfloat16(x);
    *hp = h;
    *lp = __float2bfloat16(x - __bfloat162float(h));
}

// ================== generic GEMM: C = act(A@B + bias), bf16x3 tensor-core =========
// Block 128x128x32, 8 warps (2m x 4n), warp tile 64x32 (4x2 wmma 16x16x16).
// Smem: Ah/Al [128][40] halves, Bh/Bl [32][136] halves; stage [64][132] f32 (aliased).
// OUTBS remaps output row m=(s*B+b) -> (b*S+s) for the final [B,S,V] transpose.
template<bool RELU, bool OUTBS>
__global__ void __launch_bounds__(256) gemm_wmma(
    int M, int N, int K,
    const float* __restrict__ A, int lda,
    const float* __restrict__ Bm, int ldb,
    const float* __restrict__ bias,
    float* __restrict__ C, int ldc)
{
    __shared__ __align__(16) char smraw[37888];
    __nv_bfloat16* Ah = (__nv_bfloat16*)(smraw);
    __nv_bfloat16* Al = (__nv_bfloat16*)(smraw + 10240);
    __nv_bfloat16* Bh = (__nv_bfloat16*)(smraw + 20480);
    __nv_bfloat16* Bl = (__nv_bfloat16*)(smraw + 29184);
    float* stage = (float*)smraw;   // [64][132], reused post-loop

    int tid = threadIdx.x;
    int warp = tid >> 5;
    int wm = warp >> 2, wn = warp & 3;
    int m0 = blockIdx.y << 7, n0 = blockIdx.x << 7;

    wmma::fragment<wmma::accumulator, 16, 16, 16, float> acc[4][2];
    #pragma unroll
    for (int i = 0; i < 4; i++)
        #pragma unroll
        for (int j = 0; j < 2; j++)
            wmma::fill_fragment(acc[i][j], 0.0f);

    int arow = tid >> 1, akq = (tid & 1) << 4;   // A: 128 rows x 16 k each
    int bkr = tid >> 3, bnq = (tid & 7) << 4;    // B: 32 k-rows x 16 n each

    const bool bvec = ((ldb & 3) == 0) && (n0 + 128 <= N);

    for (int k0 = 0; k0 < K; k0 += 32) {
        // ---- load A tile (always aligned, M multiple of 128 guaranteed) ----
        const float* Ap = A + (size_t)(m0 + arow)*lda + k0 + akq;
        #pragma unroll
        for (int g = 0; g < 4; g++) {
            float4 v = *(const float4*)(Ap + g*4);
            cvt_store4(v, &Ah[arow*40 + akq + g*4], &Al[arow*40 + akq + g*4]);
        }
        // ---- load B tile ----
        if (bvec) {
            const float* Bp = Bm + (size_t)(k0 + bkr)*ldb + n0 + bnq;
            #pragma unroll
            for (int g = 0; g < 4; g++) {
                float4 v = *(const float4*)(Bp + g*4);
                cvt_store4(v, &Bh[bkr*136 + bnq + g*4], &Bl[bkr*136 + bnq + g*4]);
            }
        } else {
            const float* Bp = Bm + (size_t)(k0 + bkr)*ldb;
            #pragma unroll
            for (int g = 0; g < 16; g++) {
                int n = n0 + bnq + g;
                float x = (n < N) ? Bp[n] : 0.f;
                cvt_store1(x, &Bh[bkr*136 + bnq + g], &Bl[bkr*136 + bnq + g]);
            }
        }
        __syncthreads();
        // ---- mma ----
        #pragma unroll
        for (int kk = 0; kk < 32; kk += 16) {
            wmma::fragment<wmma::matrix_b, 16, 16, 16, __nv_bfloat16, wmma::row_major> fbh[2], fbl[2];
            #pragma unroll
            for (int j = 0; j < 2; j++) {
                wmma::load_matrix_sync(fbh[j], &Bh[kk*136 + wn*32 + j*16], 136);
                wmma::load_matrix_sync(fbl[j], &Bl[kk*136 + wn*32 + j*16], 136);
            }
            #pragma unroll
            for (int i = 0; i < 4; i++) {
                wmma::fragment<wmma::matrix_a, 16, 16, 16, __nv_bfloat16, wmma::row_major> fah, fal;
                wmma::load_matrix_sync(fah, &Ah[(wm*64 + i*16)*40 + kk], 40);
                wmma::load_matrix_sync(fal, &Al[(wm*64 + i*16)*40 + kk], 40);
                #pragma unroll
                for (int j = 0; j < 2; j++) {
                    wmma::mma_sync(acc[i][j], fah, fbh[j], acc[i][j]);
                    wmma::mma_sync(acc[i][j], fah, fbl[j], acc[i][j]);
                    wmma::mma_sync(acc[i][j], fal, fbh[j], acc[i][j]);
                }
            }
        }
        __syncthreads();
    }

    // ---- staged epilogue: bias + relu + (transpose) store ----
    const bool valigned = ((ldc & 3) == 0);
    #pragma unroll
    for (int ph = 0; ph < 2; ph++) {
        if (wm == ph) {
            #pragma unroll
            for (int i = 0; i < 4; i++)
                #pragma unroll
                for (int j = 0; j < 2; j++)
                    wmma::store_matrix_sync(&stage[(i*16)*132 + wn*32 + j*16],
                                            acc[i][j], 132, wmma::mem_row_major);
        }
        __syncthreads();
        int r = tid >> 2;                  // 0..63
        int c0 = (tid & 3) << 5;           // 0,32,64,96
        int m = m0 + ph*64 + r;
        int orow = OUTBS ? ((m & 1)*S_ + (m >> 1)) : m;
        float* crow = C + (size_t)orow*ldc;
        const float* srow = stage + r*132 + c0;
        int nb = n0 + c0;
        if (valigned && nb + 32 <= N) {
            #pragma unroll
            for (int g = 0; g < 8; g++) {
                float4 v = *(const float4*)(srow + g*4);
                float4 bb = *(const float4*)(bias + nb + g*4);
                v.x += bb.x; v.y += bb.y; v.z += bb.z; v.w += bb.w;
                if (RELU) {
                    v.x = fmaxf(v.x, 0.f); v.y = fmaxf(v.y, 0.f);
                    v.z = fmaxf(v.z, 0.f); v.w = fmaxf(v.w, 0.f);
                }
                *(float4*)(crow + nb + g*4) = v;
            }
        } else {
            for (int g = 0; g < 32; g++) {
                int n = nb + g;
                if (n < N) {
                    float v = srow[g] + bias[n];
                    if (RELU) v = fmaxf(v, 0.f);
                    crow[n] = v;
                }
            }
        }
        __syncthreads();
    }
}

// ================== QK scores (NT gemm, bf16x3): P = scale * Q.K^T ================
// Per (src,bh): M=N=256, K=128. Q/K rows have stride B*D=2048.
__global__ void __launch_bounds__(256) qk_wmma(
    const float* __restrict__ Q, const float* __restrict__ Kb, float* __restrict__ P)
{
    __shared__ __align__(16) char smraw[40960];
    __nv_bfloat16* Ah = (__nv_bfloat16*)(smraw);
    __nv_bfloat16* Al = (__nv_bfloat16*)(smraw + 10240);
    __nv_bfloat16* Bh = (__nv_bfloat16*)(smraw + 20480);
    __nv_bfloat16* Bl = (__nv_bfloat16*)(smraw + 30720);

    int z = blockIdx.z;
    int src = z >> 4, bh = z & 15;
    const float* Aq = Q + bh*HD_;
    const float* Bk = Kb + (size_t)src*SBD_ + bh*HD_;
    float* Cp = P + (size_t)z*S_*S_;

    int tid = threadIdx.x;
    int warp = tid >> 5;
    int wm = warp >> 2, wn = warp & 3;
    int m0 = blockIdx.y << 7, n0 = blockIdx.x << 7;

    wmma::fragment<wmma::accumulator, 16, 16, 16, float> acc[4][2];
    #pragma unroll
    for (int i = 0; i < 4; i++)
        #pragma unroll
        for (int j = 0; j < 2; j++)
            wmma::fill_fragment(acc[i][j], 0.0f);

    int arow = tid >> 1, akq = (tid & 1) << 4;

    for (int k0 = 0; k0 < HD_; k0 += 32) {
        const float* Ap = Aq + (size_t)(m0 + arow)*(B_*D_) + k0 + akq;
        const float* Bp = Bk + (size_t)(n0 + arow)*(B_*D_) + k0 + akq;
        #pragma unroll
        for (int g = 0; g < 4; g++) {
            float4 va = *(const float4*)(Ap + g*4);
            cvt_store4(va, &Ah[arow*40 + akq + g*4], &Al[arow*40 + akq + g*4]);
            float4 vb = *(const float4*)(Bp + g*4);
            cvt_store4(vb, &Bh[arow*40 + akq + g*4], &Bl[arow*40 + akq + g*4]);
        }
        __syncthreads();
        #pragma unroll
        for (int kk = 0; kk < 32; kk += 16) {
            wmma::fragment<wmma::matrix_b, 16, 16, 16, __nv_bfloat16, wmma::col_major> fbh[2], fbl[2];
            #pragma unroll
            for (int j = 0; j < 2; j++) {
                wmma::load_matrix_sync(fbh[j], &Bh[(wn*32 + j*16)*40 + kk], 40);
                wmma::load_matrix_sync(fbl[j], &Bl[(wn*32 + j*16)*40 + kk], 40);
            }
            #pragma unroll
            for (int i = 0; i < 4; i++) {
                wmma::fragment<wmma::matrix_a, 16, 16, 16, __nv_bfloat16, wmma::row_major> fah, fal;
                wmma::load_matrix_sync(fah, &Ah[(wm*64 + i*16)*40 + kk], 40);
                wmma::load_matrix_sync(fal, &Al[(wm*64 + i*16)*40 + kk], 40);
                #pragma unroll
                for (int j = 0; j < 2; j++) {
                    wmma::mma_sync(acc[i][j], fah, fbh[j], acc[i][j]);
                    wmma::mma_sync(acc[i][j], fah, fbl[j], acc[i][j]);
                    wmma::mma_sync(acc[i][j], fal, fbh[j], acc[i][j]);
                }
            }
        }
        __syncthreads();
    }
    const float scale = 0.0883883476483184f; // 1/sqrt(128)
    #pragma unroll
    for (int i = 0; i < 4; i++)
        #pragma unroll
        for (int j = 0; j < 2; j++) {
            #pragma unroll
            for (int e = 0; e < acc[i][j].num_elements; e++) acc[i][j].x[e] *= scale;
            wmma::store_matrix_sync(&Cp[(size_t)(m0 + wm*64 + i*16)*S_ + n0 + wn*32 + j*16],
                                    acc[i][j], S_, wmma::mem_row_major);
        }
}

// ================== comb = sum_src (weighted P) @ V, bf16x3 =======================
// Per bh: M=256 (q), N=128 (hd), K=256*nsrc. Output into [S,B,D] layout.
__global__ void __launch_bounds__(256) comb_wmma(
    int nsrc, const float* __restrict__ P, const float* __restrict__ Vb,
    float* __restrict__ Cc)
{
    __shared__ __align__(16) char smraw[37888];
    __nv_bfloat16* Ah = (__nv_bfloat16*)(smraw);
    __nv_bfloat16* Al = (__nv_bfloat16*)(smraw + 10240);
    __nv_bfloat16* Bh = (__nv_bfloat16*)(smraw + 20480);
    __nv_bfloat16* Bl = (__nv_bfloat16*)(smraw + 29184);

    int bh = blockIdx.z, b = bh >> 3, h = bh & 7;
    int tid = threadIdx.x;
    int warp = tid >> 5;
    int wm = warp >> 2, wn = warp & 3;
    int m0 = blockIdx.y << 7;

    wmma::fragment<wmma::accumulator, 16, 16, 16, float> acc[4][2];
    #pragma unroll
    for (int i = 0; i < 4; i++)
        #pragma unroll
        for (int j = 0; j < 2; j++)
            wmma::fill_fragment(acc[i][j], 0.0f);

    int arow = tid >> 1, akq = (tid & 1) << 4;
    int bkr = tid >> 3, bnq = (tid & 7) << 4;

    for (int src = 0; src < nsrc; src++) {
        const float* Ap0 = P + ((size_t)src*16 + bh)*S_*S_;
        const float* Bv0 = Vb + (size_t)src*SBD_ + bh*HD_;
        for (int k0 = 0; k0 < S_; k0 += 32) {
            const float* Ap = Ap0 + (size_t)(m0 + arow)*S_ + k0 + akq;
            #pragma unroll
            for (int g = 0; g < 4; g++) {
                float4 v = *(const float4*)(Ap + g*4);
                cvt_store4(v, &Ah[arow*40 + akq + g*4], &Al[arow*40 + akq + g*4]);
            }
            const float* Bp = Bv0 + (size_t)(k0 + bkr)*(B_*D_) + bnq;
            #pragma unroll
            for (int g = 0; g < 4; g++) {
                float4 v = *(const float4*)(Bp + g*4);
                cvt_store4(v, &Bh[bkr*136 + bnq + g*4], &Bl[bkr*136 + bnq + g*4]);
            }
            __syncthreads();
            #pragma unroll
            for (int kk = 0; kk < 32; kk += 16) {
                wmma::fragment<wmma::matrix_b, 16, 16, 16, __nv_bfloat16, wmma::row_major> fbh[2], fbl[2];
                #pragma unroll
                for (int j = 0; j < 2; j++) {
                    wmma::load_matrix_sync(fbh[j], &Bh[kk*136 + wn*32 + j*16], 136);
                    wmma::load_matrix_sync(fbl[j], &Bl[kk*136 + wn*32 + j*16], 136);
                }
                #pragma unroll
                for (int i = 0; i < 4; i++) {
                    wmma::fragment<wmma::matrix_a, 16, 16, 16, __nv_bfloat16, wmma::row_major> fah, fal;
                    wmma::load_matrix_sync(fah, &Ah[(wm*64 + i*16)*40 + kk], 40);
                    wmma::load_matrix_sync(fal, &Al[(wm*64 + i*16)*40 + kk], 40);
                    #pragma unroll
                    for (int j = 0; j < 2; j++) {
                        wmma::mma_sync(acc[i][j], fah, fbh[j], acc[i][j]);
                        wmma::mma_sync(acc[i][j], fah, fbl[j], acc[i][j]);
                        wmma::mma_sync(acc[i][j], fal, fbh[j], acc[i][j]);
                    }
                }
            }
            __syncthreads();
        }
    }
    // direct store into [S,B,D]: row q -> offset (q*B + b)*D + h*HD
    #pragma unroll
    for (int i = 0; i < 4; i++) {
        int q = m0 + wm*64 + i*16;
        #pragma unroll
        for (int j = 0; j < 2; j++)
            wmma::store_matrix_sync(&Cc[((size_t)q*B_ + b)*D_ + h*HD_ + wn*32 + j*16],
                                    acc[i][j], B_*D_, wmma::mem_row_major);
    }
}

// ---------------- softmax over keys + apply layer weight -------------------------
__global__ void __launch_bounds__(256) softmax_kernel(float* __restrict__ P,
                                                      const float* __restrict__ dwl)
{
    int r = blockIdx.x*8 + (threadIdx.x >> 5);
    int lane = threadIdx.x & 31;
    float* row = P + (size_t)r*256;
    float w = dwl[r >> 12];
    float v[8];
    #pragma unroll
    for (int i = 0; i < 8; i++) v[i] = row[lane*8 + i];
    float mx = v[0];
    #pragma unroll
    for (int i = 1; i < 8; i++) mx = fmaxf(mx, v[i]);
    #pragma unroll
    for (int o = 16; o; o >>= 1) mx = fmaxf(mx, __shfl_xor_sync(0xffffffffu, mx, o));
    float s = 0.f;
    #pragma unroll
    for (int i = 0; i < 8; i++) { v[i] = expf(v[i] - mx); s += v[i]; }
    #pragma unroll
    for (int o = 16; o; o >>= 1) s += __shfl_xor_sync(0xffffffffu, s, o);
    float sc = w / s;
    #pragma unroll
    for (int i = 0; i < 8; i++) row[lane*8 + i] = v[i] * sc;
}

// ---------------- embedding + sinusoidal positional encoding ---------------------
__global__ void __launch_bounds__(256) embed_kernel(const int* __restrict__ src,
                                                    const float* __restrict__ emb,
                                                    float* __restrict__ X)
{
    int row = blockIdx.x;         // row = s*B + b
    int s = row >> 1, b = row & 1;
    int tok = src[b*S_ + s];
    const float* e = emb + (size_t)tok*D_;
    float* xr = X + (size_t)row*D_;
    const float c = -9.210340371976184f / (float)D_;  // -ln(10000)/D
    #pragma unroll
    for (int i = 0; i < 4; i++) {
        int d = threadIdx.x + (i << 8);
        int ev = d & ~1;
        float div = expf((float)ev * c);
        float arg = (float)s * div;
        float pe = (d & 1) ? cosf(arg) : sinf(arg);
        xr[d] = e[d]*32.0f + pe;   // sqrt(1024)=32
    }
}

// ---------------- distinct-source layer weights ----------------------------------
__global__ void dw_kernel(const float* __restrict__ lw, float* __restrict__ dw)
{
    int l = threadIdx.x;
    if (l >= L_) return;
    int n = l + 1;
    float w[17];
    float mx = -1e30f;
    for (int j = 0; j < n; j++) { w[j] = lw[l*(L_+1) + j]; mx = fmaxf(mx, w[j]); }
    float s = 0.f;
    for (int j = 0; j < n; j++) { w[j] = expf(w[j] - mx); s += w[j]; }
    for (int j = 0; j < n; j++) w[j] /= s;
    if (l == 0) dw[0] = w[0];
    else for (int j = 0; j < l; j++) dw[l*16 + j] = w[j+1] + ((j == l-1) ? w[0] : 0.f);
}

// ---------------- residual add + LayerNorm ----------------------------------------
__global__ void __launch_bounds__(256) addln_kernel(const float* __restrict__ x,
                                                    const float* __restrict__ r,
                                                    const float* __restrict__ g,
                                                    const float* __restrict__ be,
                                                    float* __restrict__ out)
{
    int row = blockIdx.x;
    const float* xr = x + (size_t)row*D_;
    const float* rr = r + (size_t)row*D_;
    int lane = threadIdx.x & 31, wid = threadIdx.x >> 5;
    float v[4];
    float s = 0.f, sq = 0.f;
    #pragma unroll
    for (int i = 0; i < 4; i++) {
        int d = threadIdx.x + (i << 8);
        float a = xr[d] + rr[d];
        v[i] = a; s += a; sq += a*a;
    }
    #pragma unroll
    for (int o = 16; o; o >>= 1) {
        s  += __shfl_xor_sync(0xffffffffu, s, o);
        sq += __shfl_xor_sync(0xffffffffu, sq, o);
    }
    __shared__ float shs[8], shq[8], mv[2];
    if (lane == 0) { shs[wid] = s; shq[wid] = sq; }
    __syncthreads();
    if (wid == 0) {
        float a = (lane < 8) ? shs[lane] : 0.f;
        float b = (lane < 8) ? shq[lane] : 0.f;
        #pragma unroll
        for (int o = 4; o; o >>= 1) {
            a += __shfl_xor_sync(0xffffffffu, a, o);
            b += __shfl_xor_sync(0xffffffffu, b, o);
        }
        if (lane == 0) {
            float mean = a * (1.f/ (float)D_);
            float var  = b * (1.f/ (float)D_) - mean*mean;
            mv[0] = mean; mv[1] = rsqrtf(var + 1e-5f);
        }
    }
    __syncthreads();
    float mean = mv[0], rstd = mv[1];
    float* orow = out + (size_t)row*D_;
    #pragma unroll
    for (int i = 0; i < 4; i++) {
        int d = threadIdx.x + (i << 8);
        orow[d] = (v[i] - mean)*rstd*g[d] + be[d];
    }
}

// ---------------- SNN scan: sequential over S steps, one block per batch ----------
__global__ void __launch_bounds__(256) snn_kernel(const float* __restrict__ cur,
                                                  float* __restrict__ spikes)
{
    int b = blockIdx.x;
    int lane = threadIdx.x & 31, wid = threadIdx.x >> 5;
    float mem[4] = {0.f,0.f,0.f,0.f};
    float thr[4] = {1.f,1.f,1.f,1.f};
    __shared__ float sh[8];
    __shared__ float tot[2];
    for (int t = 0; t < S_; t++) {
        float p = mem[0]+mem[1]+mem[2]+mem[3];
        #pragma unroll
        for (int o = 16; o; o >>= 1) p += __shfl_xor_sync(0xffffffffu, p, o);
        if (lane == 0) sh[wid] = p;
        __syncthreads();
        if (wid == 0) {
            float v = (lane < 8) ? sh[lane] : 0.f;
            #pragma unroll
            for (int o = 4; o; o >>= 1) v += __shfl_xor_sync(0xffffffffu, v, o);
            if (lane == 0) tot[t & 1] = v;
        }
        __syncthreads();
        float M = tot[t & 1];
        const float* cr = cur    + ((size_t)t*B_ + b)*D_;
        float*       sr = spikes + ((size_t)t*B_ + b)*D_;
        #pragma unroll
        for (int i = 0; i < 4; i++) {
            int d = threadIdx.x + (i << 8);
            float c  = cr[d] - 0.1f*M;
            float m2 = 0.9f*mem[i] + c;
            float sp = (m2 >= thr[i]) ? 1.f : 0.f;
            mem[i] = m2 - sp*thr[i];
            thr[i] = 0.9f*thr[i] + 0.1f*sp;
            sr[d] = sp;
        }
    }
}

// ---------------- host orchestration ---------------------------------------------
extern "C" void kernel_launch(void* const* d_in, const int* in_sizes, int n_in,
                              void* d_out, int out_size)
{
    const int*   src  = (const int*)  d_in[0];
    const float* emb  = (const float*)d_in[1];
    const float* Wq   = (const float*)d_in[2];
    const float* bq   = (const float*)d_in[3];
    const float* Wk   = (const float*)d_in[4];
    const float* bk   = (const float*)d_in[5];
    const float* Wv   = (const float*)d_in[6];
    const float* bv   = (const float*)d_in[7];
    const float* Wo   = (const float*)d_in[8];
    const float* bo   = (const float*)d_in[9];
    const float* lw   = (const float*)d_in[10];
    const float* Wsnn = (const float*)d_in[11];
    const float* bsnn = (const float*)d_in[12];
    const float* W1   = (const float*)d_in[13];
    const float* b1   = (const float*)d_in[14];
    const float* W2   = (const float*)d_in[15];
    const float* b2   = (const float*)d_in[16];
    const float* g1   = (const float*)d_in[17];
    const float* be1  = (const float*)d_in[18];
    const float* g2   = (const float*)d_in[19];
    const float* be2  = (const float*)d_in[20];
    const float* Wout = (const float*)d_in[21];
    const float* bout = (const float*)d_in[22];
    float* out = (float*)d_out;

    float *x0,*lo,*q,*kb,*vb,*sc,*comb,*xa,*t2,*tff,*sp,*dw;
    cudaGetSymbolAddress((void**)&x0,   g_x0);
    cudaGetSymbolAddress((void**)&lo,   g_lo);
    cudaGetSymbolAddress((void**)&q,    g_q);
    cudaGetSymbolAddress((void**)&kb,   g_k);
    cudaGetSymbolAddress((void**)&vb,   g_v);
    cudaGetSymbolAddress((void**)&sc,   g_sc);
    cudaGetSymbolAddress((void**)&comb, g_comb);
    cudaGetSymbolAddress((void**)&xa,   g_xa);
    cudaGetSymbolAddress((void**)&t2,   g_t2);
    cudaGetSymbolAddress((void**)&tff,  g_tff);
    cudaGetSymbolAddress((void**)&sp,   g_sp);
    cudaGetSymbolAddress((void**)&dw,   g_dw);

    embed_kernel<<<SB_, 256>>>(src, emb, x0);
    dw_kernel<<<1, 32>>>(lw, dw);

    for (int l = 0; l < L_; l++) {
        int nsrc = (l == 0) ? 1 : l;
        const float* srcbase = (l == 0) ? x0 : lo;
        const float* xin     = (l == 0) ? x0 : (lo + (size_t)(l-1)*SBD_);
        int Ms = nsrc * SB_;

        gemm_wmma<false,false><<<dim3(D_/128, Ms/128), 256>>>(
            Ms, D_, D_, srcbase, D_, Wk + (size_t)l*D_*D_, D_, bk + l*D_, kb, D_);
        gemm_wmma<false,false><<<dim3(D_/128, Ms/128), 256>>>(
            Ms, D_, D_, srcbase, D_, Wv + (size_t)l*D_*D_, D_, bv + l*D_, vb, D_);
        gemm_wmma<false,false><<<dim3(D_/128, SB_/128), 256>>>(
            SB_, D_, D_, xin, D_, Wq + (size_t)l*D_*D_, D_, bq + l*D_, q, D_);

        qk_wmma<<<dim3(2, 2, nsrc*16), 256>>>(q, kb, sc);
        softmax_kernel<<<nsrc*512, 256>>>(sc, dw + l*16);
        comb_wmma<<<dim3(1, 2, 16), 256>>>(nsrc, sc, vb, comb);

        gemm_wmma<false,false><<<dim3(D_/128, SB_/128), 256>>>(
            SB_, D_, D_, comb, D_, Wo + (size_t)l*D_*D_, D_, bo + l*D_, t2, D_);
        addln_kernel<<<SB_, 256>>>(xin, t2, g1 + l*D_, be1 + l*D_, xa);

        gemm_wmma<false,false><<<dim3(D_/128, SB_/128), 256>>>(
            SB_, D_, D_, xa, D_, Wsnn + (size_t)l*D_*D_, D_, bsnn + l*D_, t2, D_);
        snn_kernel<<<B_, 256>>>(t2, sp);

        gemm_wmma<true,false><<<dim3(FF_/128, SB_/128), 256>>>(
            SB_, FF_, D_, sp, D_, W1 + (size_t)l*D_*FF_, FF_, b1 + l*FF_, tff, FF_);
        gemm_wmma<false,false><<<dim3(D_/128, SB_/128), 256>>>(
            SB_, D_, FF_, tff, FF_, W2 + (size_t)l*FF_*D_, D_, b2 + l*D_, t2, D_);
        addln_kernel<<<SB_, 256>>>(xa, t2, g2 + l*D_, be2 + l*D_, lo + (size_t)l*SBD_);
    }

    gemm_wmma<false,true><<<dim3((V_+127)/128, SB_/128), 256>>>(
        SB_, V_, D_, lo + (size_t)15*SBD_, D_, Wout, V_, bout, out, V_);
}